// round 4
// baseline (speedup 1.0000x reference)
#include <cuda_runtime.h>
#include <math.h>

// ---------------- problem constants ----------------
#define NN   50000
#define NE   1600000
#define EPAD (NE + NN)        // edges + self loops
#define NF   512
#define H1   8
#define C1   16
#define HC1  128
#define C2   16

// ---------------- scratch (device globals) ----------------
__device__ float g_h1[NN * HC1];
__device__ float g_as1[NN * H1];
__device__ float g_ad1[NN * H1];
__device__ float g_out1[NN * HC1];
__device__ float g_h2[NN * C2];
__device__ float g_as2[NN];
__device__ float g_ad2[NN];
__device__ float g_out2[NN * C2];
__device__ int   g_cnt[NN];
__device__ int   g_rowptr[NN + 1];
__device__ int   g_cursor[NN];
__device__ int   g_col[EPAD];

// ================= CSR build =================
__global__ void fill_int(int* p, int v, int n) {
    int i = blockIdx.x * blockDim.x + threadIdx.x;
    if (i < n) p[i] = v;
}

__global__ void count_dst(const int* __restrict__ ei, int* __restrict__ cnt, int E) {
    int e = blockIdx.x * blockDim.x + threadIdx.x;
    if (e < E) atomicAdd(&cnt[ei[E + e]], 1);
}

// single-block exclusive scan over NN counts -> rowptr[NN+1]
__global__ void scan_rowptr(const int* __restrict__ cnt, int* __restrict__ rowptr) {
    __shared__ int ssum[1024];
    const int T = 1024;
    const int PER = (NN + T - 1) / T;   // 49
    int tid = threadIdx.x;
    int start = tid * PER;
    int local = 0;
    for (int i = 0; i < PER; i++) {
        int idx = start + i;
        if (idx < NN) local += cnt[idx];
    }
    ssum[tid] = local;
    __syncthreads();
    // Hillis-Steele inclusive scan
    for (int off = 1; off < T; off <<= 1) {
        int v = (tid >= off) ? ssum[tid - off] : 0;
        __syncthreads();
        ssum[tid] += v;
        __syncthreads();
    }
    int run = (tid == 0) ? 0 : ssum[tid - 1];
    for (int i = 0; i < PER; i++) {
        int idx = start + i;
        if (idx < NN) { rowptr[idx] = run; run += cnt[idx]; }
    }
    if (tid == T - 1) rowptr[NN] = ssum[T - 1];
}

__global__ void copy_cursor(const int* __restrict__ rowptr, int* __restrict__ cursor) {
    int i = blockIdx.x * blockDim.x + threadIdx.x;
    if (i < NN) cursor[i] = rowptr[i];
}

// scatter E edges + NN self loops into col[]
__global__ void scatter_edges(const int* __restrict__ ei, int* __restrict__ cursor,
                              int* __restrict__ col, int E) {
    int i = blockIdx.x * blockDim.x + threadIdx.x;
    int tot = E + NN;
    if (i >= tot) return;
    int s, d;
    if (i < E) { s = ei[i]; d = ei[E + i]; } else { s = d = i - E; }
    int pos = atomicAdd(&cursor[d], 1);
    col[pos] = s;
}

// ================= SGEMM (NT): C[M,N] = A[M,K]*B[N,K]^T =================
#define GBM 128
#define GBN 128
#define GBK 8

__global__ __launch_bounds__(256, 2)
void gemm_nt(const float* __restrict__ A, const float* __restrict__ B,
             float* __restrict__ C, int M, int Nn, int K) {
    __shared__ float As[GBK][GBM];
    __shared__ float Bs[GBK][GBN];
    int t = threadIdx.x;
    int tx = t & 15, ty = t >> 4;          // 16x16 threads, 8x8 each
    int m0 = blockIdx.y * GBM, n0 = blockIdx.x * GBN;
    int lrow = t >> 1;                      // 0..127
    int lk = (t & 1) * 4;                   // 0 or 4

    float acc[8][8];
    #pragma unroll
    for (int i = 0; i < 8; i++)
        #pragma unroll
        for (int j = 0; j < 8; j++) acc[i][j] = 0.f;

    for (int k0 = 0; k0 < K; k0 += GBK) {
        float4 av = make_float4(0.f, 0.f, 0.f, 0.f);
        float4 bv = make_float4(0.f, 0.f, 0.f, 0.f);
        int am = m0 + lrow;
        if (am < M) av = *reinterpret_cast<const float4*>(&A[(size_t)am * K + k0 + lk]);
        int bn = n0 + lrow;
        if (bn < Nn) bv = *reinterpret_cast<const float4*>(&B[(size_t)bn * K + k0 + lk]);
        As[lk + 0][lrow] = av.x; As[lk + 1][lrow] = av.y;
        As[lk + 2][lrow] = av.z; As[lk + 3][lrow] = av.w;
        Bs[lk + 0][lrow] = bv.x; Bs[lk + 1][lrow] = bv.y;
        Bs[lk + 2][lrow] = bv.z; Bs[lk + 3][lrow] = bv.w;
        __syncthreads();
        #pragma unroll
        for (int k = 0; k < GBK; k++) {
            float a[8], b[8];
            float4 a0 = *reinterpret_cast<const float4*>(&As[k][ty * 8]);
            float4 a1 = *reinterpret_cast<const float4*>(&As[k][ty * 8 + 4]);
            float4 b0 = *reinterpret_cast<const float4*>(&Bs[k][tx * 8]);
            float4 b1 = *reinterpret_cast<const float4*>(&Bs[k][tx * 8 + 4]);
            a[0]=a0.x;a[1]=a0.y;a[2]=a0.z;a[3]=a0.w;a[4]=a1.x;a[5]=a1.y;a[6]=a1.z;a[7]=a1.w;
            b[0]=b0.x;b[1]=b0.y;b[2]=b0.z;b[3]=b0.w;b[4]=b1.x;b[5]=b1.y;b[6]=b1.z;b[7]=b1.w;
            #pragma unroll
            for (int i = 0; i < 8; i++)
                #pragma unroll
                for (int j = 0; j < 8; j++) acc[i][j] += a[i] * b[j];
        }
        __syncthreads();
    }
    #pragma unroll
    for (int i = 0; i < 8; i++) {
        int m = m0 + ty * 8 + i;
        if (m >= M) continue;
        #pragma unroll
        for (int j = 0; j < 8; j++) {
            int n = n0 + tx * 8 + j;
            if (n < Nn) C[(size_t)m * Nn + n] = acc[i][j];
        }
    }
}

// ================= attention coefficients =================
__global__ void att_kernel(const float* __restrict__ h, const float* __restrict__ att_s,
                           const float* __restrict__ att_d, float* __restrict__ as_,
                           float* __restrict__ ad_, int N, int H, int C) {
    int idx = blockIdx.x * blockDim.x + threadIdx.x;
    if (idx >= N * H) return;
    int n = idx / H, hh = idx - n * H;
    const float* hp = h + ((size_t)n * H + hh) * C;
    float s = 0.f, d = 0.f;
    for (int c = 0; c < C; c++) {
        float v = hp[c];
        s += v * att_s[hh * C + c];
        d += v * att_d[hh * C + c];
    }
    as_[idx] = s;
    ad_[idx] = d;
}

// ================= fused GAT aggregate: one warp per (dst, head) =================
// C must be 16. APPLY_ELU: fuse bias+ELU (layer 1). bias layout [H*C].
template<int H, bool APPLY_ELU>
__global__ void gat_aggregate(const int* __restrict__ rowptr, const int* __restrict__ col,
                              const float* __restrict__ as_, const float* __restrict__ ad_,
                              const float* __restrict__ hfeat, const float* __restrict__ bias,
                              float* __restrict__ out) {
    const int C = 16;
    int gw = (blockIdx.x * blockDim.x + threadIdx.x) >> 5;
    int lane = threadIdx.x & 31;
    if (gw >= NN * H) return;
    int dst = gw / H, head = gw - dst * H;

    int beg = rowptr[dst], end = rowptr[dst + 1];
    float adv = ad_[dst * H + head];

    // pass 1: max
    float m = -INFINITY;
    for (int i = beg + lane; i < end; i += 32) {
        float v = as_[col[i] * H + head] + adv;
        v = v > 0.f ? v : 0.2f * v;
        m = fmaxf(m, v);
    }
    #pragma unroll
    for (int o = 16; o > 0; o >>= 1) m = fmaxf(m, __shfl_xor_sync(0xffffffffu, m, o));

    // pass 2: sum of exp
    float s = 0.f;
    for (int i = beg + lane; i < end; i += 32) {
        float v = as_[col[i] * H + head] + adv;
        v = v > 0.f ? v : 0.2f * v;
        s += __expf(v - m);
    }
    #pragma unroll
    for (int o = 16; o > 0; o >>= 1) s += __shfl_xor_sync(0xffffffffu, s, o);

    // pass 3: weighted aggregate; 2 edges per iter, 16 channels each
    int c = lane & 15;
    int sub = lane >> 4;
    float acc = 0.f;
    for (int i = beg + sub; i < end; i += 2) {
        int src = col[i];
        float v = as_[src * H + head] + adv;
        v = v > 0.f ? v : 0.2f * v;
        float w = __expf(v - m);
        acc += w * hfeat[((size_t)src * H + head) * C + c];
    }
    acc += __shfl_down_sync(0xffffffffu, acc, 16);
    if (lane < 16) {
        float r = acc / (s + 1e-16f);
        if (APPLY_ELU) {
            r += bias[head * C + c];
            r = r > 0.f ? r : expm1f(r);
        }
        out[((size_t)dst * H + head) * C + c] = r;
    }
}

// ================= final bias + log_softmax =================
__global__ void final_lsm(const float* __restrict__ in, const float* __restrict__ b,
                          float* __restrict__ out, int N) {
    int n = blockIdx.x * blockDim.x + threadIdx.x;
    if (n >= N) return;
    float v[C2];
    float m = -INFINITY;
    #pragma unroll
    for (int c = 0; c < C2; c++) {
        v[c] = in[(size_t)n * C2 + c] + b[c];
        m = fmaxf(m, v[c]);
    }
    float s = 0.f;
    #pragma unroll
    for (int c = 0; c < C2; c++) s += __expf(v[c] - m);
    float l = __logf(s);
    #pragma unroll
    for (int c = 0; c < C2; c++) out[(size_t)n * C2 + c] = v[c] - m - l;
}

// ================= launch =================
extern "C" void kernel_launch(void* const* d_in, const int* in_sizes, int n_in,
                              void* d_out, int out_size) {
    const float* x    = (const float*)d_in[0];
    const int*   ei   = (const int*)d_in[1];
    const float* W1   = (const float*)d_in[2];
    const float* at1s = (const float*)d_in[3];
    const float* at1d = (const float*)d_in[4];
    const float* b1   = (const float*)d_in[5];
    const float* W2   = (const float*)d_in[6];
    const float* at2s = (const float*)d_in[7];
    const float* at2d = (const float*)d_in[8];
    const float* b2   = (const float*)d_in[9];
    float* out = (float*)d_out;

    int E = in_sizes[1] / 2;

    static float *p_h1 = nullptr, *p_as1, *p_ad1, *p_out1, *p_h2, *p_as2, *p_ad2, *p_out2;
    static int *p_cnt, *p_rowptr, *p_cursor, *p_col;
    if (!p_h1) {
        cudaGetSymbolAddress((void**)&p_h1, g_h1);
        cudaGetSymbolAddress((void**)&p_as1, g_as1);
        cudaGetSymbolAddress((void**)&p_ad1, g_ad1);
        cudaGetSymbolAddress((void**)&p_out1, g_out1);
        cudaGetSymbolAddress((void**)&p_h2, g_h2);
        cudaGetSymbolAddress((void**)&p_as2, g_as2);
        cudaGetSymbolAddress((void**)&p_ad2, g_ad2);
        cudaGetSymbolAddress((void**)&p_out2, g_out2);
        cudaGetSymbolAddress((void**)&p_cnt, g_cnt);
        cudaGetSymbolAddress((void**)&p_rowptr, g_rowptr);
        cudaGetSymbolAddress((void**)&p_cursor, g_cursor);
        cudaGetSymbolAddress((void**)&p_col, g_col);
    }

    const int TB = 256;
    auto blocks = [](int n, int tb) { return (n + tb - 1) / tb; };

    // ---- CSR build (shared by both layers) ----
    fill_int<<<blocks(NN, TB), TB>>>(p_cnt, 1, NN);                 // 1 = self loop
    count_dst<<<blocks(E, TB), TB>>>(ei, p_cnt, E);
    scan_rowptr<<<1, 1024>>>(p_cnt, p_rowptr);
    copy_cursor<<<blocks(NN, TB), TB>>>(p_rowptr, p_cursor);
    scatter_edges<<<blocks(E + NN, TB), TB>>>(ei, p_cursor, p_col, E);

    // ---- layer 1 ----
    {
        dim3 grid((HC1 + GBN - 1) / GBN, (NN + GBM - 1) / GBM);
        gemm_nt<<<grid, 256>>>(x, W1, p_h1, NN, HC1, NF);
    }
    att_kernel<<<blocks(NN * H1, TB), TB>>>(p_h1, at1s, at1d, p_as1, p_ad1, NN, H1, C1);
    gat_aggregate<H1, true><<<blocks(NN * H1 * 32, TB), TB>>>(
        p_rowptr, p_col, p_as1, p_ad1, p_h1, b1, p_out1);

    // ---- layer 2 ----
    {
        dim3 grid((C2 + GBN - 1) / GBN, (NN + GBM - 1) / GBM);
        gemm_nt<<<grid, 256>>>(p_out1, W2, p_h2, NN, C2, HC1);
    }
    att_kernel<<<blocks(NN, TB), TB>>>(p_h2, at2s, at2d, p_as2, p_ad2, NN, 1, C2);
    gat_aggregate<1, false><<<blocks(NN * 32, TB), TB>>>(
        p_rowptr, p_col, p_as2, p_ad2, p_h2, nullptr, p_out2);

    // ---- log_softmax ----
    final_lsm<<<blocks(NN, TB), TB>>>(p_out2, b2, out, NN);
}

// round 5
// speedup vs baseline: 1.1579x; 1.1579x over previous
#include <cuda_runtime.h>
#include <math.h>

// ---------------- problem constants ----------------
#define NN   50000
#define NE   1600000
#define EPAD (NE + NN)
#define NF   512
#define H1   8
#define C1   16
#define HC1  128
#define C2   16

// ---------------- scratch (device globals) ----------------
__device__ float g_h1[NN * HC1];
__device__ float g_as1[NN * H1];
__device__ float g_ad1[NN * H1];
__device__ float g_out1[NN * HC1];
__device__ float g_h2[NN * C2];
__device__ float g_as2[NN];
__device__ float g_ad2[NN];
__device__ float g_out2[NN * C2];
__device__ int   g_cnt[NN];
__device__ int   g_rowptr[NN + 1];
__device__ int   g_cursor[NN];
__device__ int   g_col[EPAD];

// ================= CSR build =================
__global__ void fill_int(int* p, int v, int n) {
    int i = blockIdx.x * blockDim.x + threadIdx.x;
    if (i < n) p[i] = v;
}

__global__ void count_dst(const int* __restrict__ ei, int* __restrict__ cnt, int E) {
    int e = blockIdx.x * blockDim.x + threadIdx.x;
    if (e < E) atomicAdd(&cnt[ei[E + e]], 1);
}

// single-block exclusive scan over NN counts -> rowptr[NN+1] and cursor[NN]
__global__ void scan_rowptr(const int* __restrict__ cnt, int* __restrict__ rowptr,
                            int* __restrict__ cursor) {
    __shared__ int ssum[1024];
    const int T = 1024;
    const int PER = (NN + T - 1) / T;
    int tid = threadIdx.x;
    int start = tid * PER;
    int local = 0;
    for (int i = 0; i < PER; i++) {
        int idx = start + i;
        if (idx < NN) local += cnt[idx];
    }
    ssum[tid] = local;
    __syncthreads();
    for (int off = 1; off < T; off <<= 1) {
        int v = (tid >= off) ? ssum[tid - off] : 0;
        __syncthreads();
        ssum[tid] += v;
        __syncthreads();
    }
    int run = (tid == 0) ? 0 : ssum[tid - 1];
    for (int i = 0; i < PER; i++) {
        int idx = start + i;
        if (idx < NN) { rowptr[idx] = run; cursor[idx] = run; run += cnt[idx]; }
    }
    if (tid == T - 1) rowptr[NN] = ssum[T - 1];
}

__global__ void scatter_edges(const int* __restrict__ ei, int* __restrict__ cursor,
                              int* __restrict__ col, int E) {
    int i = blockIdx.x * blockDim.x + threadIdx.x;
    int tot = E + NN;
    if (i >= tot) return;
    int s, d;
    if (i < E) { s = ei[i]; d = ei[E + i]; } else { s = d = i - E; }
    int pos = atomicAdd(&cursor[d], 1);
    col[pos] = s;
}

// ================= SGEMM (NT) with register prefetch =================
#define GBM 128
#define GBN 128
#define GBK 8

__global__ __launch_bounds__(256, 2)
void gemm_nt(const float* __restrict__ A, const float* __restrict__ B,
             float* __restrict__ C, int M, int Nn, int K) {
    __shared__ float As[GBK][GBM];
    __shared__ float Bs[GBK][GBN];
    int t = threadIdx.x;
    int tx = t & 15, ty = t >> 4;
    int m0 = blockIdx.y * GBM, n0 = blockIdx.x * GBN;
    int lrow = t >> 1;
    int lk = (t & 1) * 4;

    float acc[8][8];
    #pragma unroll
    for (int i = 0; i < 8; i++)
        #pragma unroll
        for (int j = 0; j < 8; j++) acc[i][j] = 0.f;

    int am = m0 + lrow;
    int bn = n0 + lrow;
    const float* Ap = (am < M) ? &A[(size_t)am * K + lk] : nullptr;
    const float* Bp = (bn < Nn) ? &B[(size_t)bn * K + lk] : nullptr;

    float4 av = Ap ? *reinterpret_cast<const float4*>(Ap) : make_float4(0,0,0,0);
    float4 bv = Bp ? *reinterpret_cast<const float4*>(Bp) : make_float4(0,0,0,0);

    for (int k0 = 0; k0 < K; k0 += GBK) {
        As[lk + 0][lrow] = av.x; As[lk + 1][lrow] = av.y;
        As[lk + 2][lrow] = av.z; As[lk + 3][lrow] = av.w;
        Bs[lk + 0][lrow] = bv.x; Bs[lk + 1][lrow] = bv.y;
        Bs[lk + 2][lrow] = bv.z; Bs[lk + 3][lrow] = bv.w;
        __syncthreads();
        // prefetch next tile
        if (k0 + GBK < K) {
            av = Ap ? *reinterpret_cast<const float4*>(Ap + k0 + GBK) : make_float4(0,0,0,0);
            bv = Bp ? *reinterpret_cast<const float4*>(Bp + k0 + GBK) : make_float4(0,0,0,0);
        }
        #pragma unroll
        for (int k = 0; k < GBK; k++) {
            float a[8], b[8];
            float4 a0 = *reinterpret_cast<const float4*>(&As[k][ty * 8]);
            float4 a1 = *reinterpret_cast<const float4*>(&As[k][ty * 8 + 4]);
            float4 b0 = *reinterpret_cast<const float4*>(&Bs[k][tx * 8]);
            float4 b1 = *reinterpret_cast<const float4*>(&Bs[k][tx * 8 + 4]);
            a[0]=a0.x;a[1]=a0.y;a[2]=a0.z;a[3]=a0.w;a[4]=a1.x;a[5]=a1.y;a[6]=a1.z;a[7]=a1.w;
            b[0]=b0.x;b[1]=b0.y;b[2]=b0.z;b[3]=b0.w;b[4]=b1.x;b[5]=b1.y;b[6]=b1.z;b[7]=b1.w;
            #pragma unroll
            for (int i = 0; i < 8; i++)
                #pragma unroll
                for (int j = 0; j < 8; j++) acc[i][j] += a[i] * b[j];
        }
        __syncthreads();
    }
    #pragma unroll
    for (int i = 0; i < 8; i++) {
        int m = m0 + ty * 8 + i;
        if (m >= M) continue;
        #pragma unroll
        for (int j = 0; j < 8; j++) {
            int n = n0 + tx * 8 + j;
            if (n < Nn) C[(size_t)m * Nn + n] = acc[i][j];
        }
    }
}

// ================= attention coefficients (C=16, float4) =================
template<int H>
__global__ void att_kernel(const float* __restrict__ h, const float* __restrict__ att_s,
                           const float* __restrict__ att_d, float* __restrict__ as_,
                           float* __restrict__ ad_) {
    int idx = blockIdx.x * blockDim.x + threadIdx.x;
    if (idx >= NN * H) return;
    int hh = idx & (H - 1);
    const float4* hp = reinterpret_cast<const float4*>(h) + (size_t)idx * 4;
    const float4* sp = reinterpret_cast<const float4*>(att_s) + hh * 4;
    const float4* dp = reinterpret_cast<const float4*>(att_d) + hh * 4;
    float s = 0.f, d = 0.f;
    #pragma unroll
    for (int q = 0; q < 4; q++) {
        float4 v = hp[q], a = sp[q], b = dp[q];
        s += v.x * a.x + v.y * a.y + v.z * a.z + v.w * a.w;
        d += v.x * b.x + v.y * b.y + v.z * b.z + v.w * b.w;
    }
    as_[idx] = s;
    ad_[idx] = d;
}

// ================= layer-1 fused aggregate: one warp per dst, all 8 heads =================
__global__ __launch_bounds__(256)
void gat_aggregate_l1(const int* __restrict__ rowptr, const int* __restrict__ col,
                      const float* __restrict__ as_, const float* __restrict__ ad_,
                      const float* __restrict__ hfeat, const float* __restrict__ bias,
                      float* __restrict__ out) {
    int warp = (blockIdx.x * blockDim.x + threadIdx.x) >> 5;
    int lane = threadIdx.x & 31;
    if (warp >= NN) return;
    int dst = warp;
    int beg = rowptr[dst], end = rowptr[dst + 1];

    // per-dst attention offsets (uniform across warp)
    const float4* ad4 = reinterpret_cast<const float4*>(ad_) + (size_t)dst * 2;
    float4 adl = ad4[0], adh = ad4[1];
    float ad[8] = {adl.x, adl.y, adl.z, adl.w, adh.x, adh.y, adh.z, adh.w};

    const float4* as4 = reinterpret_cast<const float4*>(as_);

    // ---- sweep 1: online softmax (m, s) for all 8 heads ----
    float m[8], s[8];
    #pragma unroll
    for (int h = 0; h < 8; h++) { m[h] = -INFINITY; s[h] = 0.f; }

    for (int i = beg + lane; i < end; i += 32) {
        int src = col[i];
        float4 a0 = as4[(size_t)src * 2];
        float4 a1 = as4[(size_t)src * 2 + 1];
        float av[8] = {a0.x, a0.y, a0.z, a0.w, a1.x, a1.y, a1.z, a1.w};
        #pragma unroll
        for (int h = 0; h < 8; h++) {
            float v = av[h] + ad[h];
            v = v > 0.f ? v : 0.2f * v;
            float nm = fmaxf(m[h], v);
            s[h] = s[h] * __expf(m[h] - nm) + __expf(v - nm);  // m=-inf -> exp(-inf)=0, safe
            m[h] = nm;
        }
    }
    // warp butterfly combine (nan-safe for empty lanes)
    #pragma unroll
    for (int o = 16; o > 0; o >>= 1) {
        #pragma unroll
        for (int h = 0; h < 8; h++) {
            float om = __shfl_xor_sync(0xffffffffu, m[h], o);
            float os = __shfl_xor_sync(0xffffffffu, s[h], o);
            float nm = fmaxf(m[h], om);
            float e1 = (m[h] == nm) ? 1.f : __expf(m[h] - nm);
            float e2 = (om == nm)   ? 1.f : __expf(om - nm);
            s[h] = s[h] * e1 + os * e2;
            m[h] = nm;
        }
    }

    // lane-specific head selection (unrolled predicated, avoids spill)
    int myh = lane >> 2;
    float mh = m[0], sh = s[0], adhd = ad[0];
    #pragma unroll
    for (int h = 1; h < 8; h++)
        if (myh == h) { mh = m[h]; sh = s[h]; adhd = ad[h]; }
    float inv = 1.f / (sh + 1e-16f);

    // ---- sweep 2: weighted aggregate, lane owns channels [lane*4, lane*4+4) ----
    const float4* h4 = reinterpret_cast<const float4*>(hfeat);
    float4 acc = make_float4(0.f, 0.f, 0.f, 0.f);
    for (int i = beg; i < end; i++) {
        int src = col[i];
        float v = as_[src * 8 + myh] + adhd;
        v = v > 0.f ? v : 0.2f * v;
        float w = __expf(v - mh);
        float4 hv = h4[(size_t)src * 32 + lane];
        acc.x += w * hv.x; acc.y += w * hv.y; acc.z += w * hv.z; acc.w += w * hv.w;
    }
    const float4* b4 = reinterpret_cast<const float4*>(bias);
    float4 bb = b4[lane];
    float4 r;
    r.x = acc.x * inv + bb.x; r.y = acc.y * inv + bb.y;
    r.z = acc.z * inv + bb.z; r.w = acc.w * inv + bb.w;
    r.x = r.x > 0.f ? r.x : expm1f(r.x);
    r.y = r.y > 0.f ? r.y : expm1f(r.y);
    r.z = r.z > 0.f ? r.z : expm1f(r.z);
    r.w = r.w > 0.f ? r.w : expm1f(r.w);
    reinterpret_cast<float4*>(out)[(size_t)dst * 32 + lane] = r;
}

// ================= layer-2 aggregate: one warp per dst, H=1, C=16 =================
__global__ __launch_bounds__(256)
void gat_aggregate_l2(const int* __restrict__ rowptr, const int* __restrict__ col,
                      const float* __restrict__ as_, const float* __restrict__ ad_,
                      const float* __restrict__ hfeat, float* __restrict__ out) {
    int warp = (blockIdx.x * blockDim.x + threadIdx.x) >> 5;
    int lane = threadIdx.x & 31;
    if (warp >= NN) return;
    int dst = warp;
    int beg = rowptr[dst], end = rowptr[dst + 1];
    float adv = ad_[dst];

    // online softmax
    float m = -INFINITY, s = 0.f;
    for (int i = beg + lane; i < end; i += 32) {
        float v = as_[col[i]] + adv;
        v = v > 0.f ? v : 0.2f * v;
        float nm = fmaxf(m, v);
        s = s * __expf(m - nm) + __expf(v - nm);
        m = nm;
    }
    #pragma unroll
    for (int o = 16; o > 0; o >>= 1) {
        float om = __shfl_xor_sync(0xffffffffu, m, o);
        float os = __shfl_xor_sync(0xffffffffu, s, o);
        float nm = fmaxf(m, om);
        float e1 = (m == nm) ? 1.f : __expf(m - nm);
        float e2 = (om == nm) ? 1.f : __expf(om - nm);
        s = s * e1 + os * e2;
        m = nm;
    }
    float inv = 1.f / (s + 1e-16f);

    // aggregate: 2 edges/iter, 16 channels
    int c = lane & 15;
    int sub = lane >> 4;
    float acc = 0.f;
    for (int i = beg + sub; i < end; i += 2) {
        int src = col[i];
        float v = as_[src] + adv;
        v = v > 0.f ? v : 0.2f * v;
        float w = __expf(v - m);
        acc += w * hfeat[(size_t)src * 16 + c];
    }
    acc += __shfl_down_sync(0xffffffffu, acc, 16);
    if (lane < 16) out[(size_t)dst * 16 + c] = acc * inv;
}

// ================= final bias + log_softmax =================
__global__ void final_lsm(const float* __restrict__ in, const float* __restrict__ b,
                          float* __restrict__ out, int N) {
    int n = blockIdx.x * blockDim.x + threadIdx.x;
    if (n >= N) return;
    float v[C2];
    float m = -INFINITY;
    #pragma unroll
    for (int c = 0; c < C2; c++) {
        v[c] = in[(size_t)n * C2 + c] + b[c];
        m = fmaxf(m, v[c]);
    }
    float s = 0.f;
    #pragma unroll
    for (int c = 0; c < C2; c++) s += __expf(v[c] - m);
    float l = __logf(s);
    #pragma unroll
    for (int c = 0; c < C2; c++) out[(size_t)n * C2 + c] = v[c] - m - l;
}

// ================= launch =================
extern "C" void kernel_launch(void* const* d_in, const int* in_sizes, int n_in,
                              void* d_out, int out_size) {
    const float* x    = (const float*)d_in[0];
    const int*   ei   = (const int*)d_in[1];
    const float* W1   = (const float*)d_in[2];
    const float* at1s = (const float*)d_in[3];
    const float* at1d = (const float*)d_in[4];
    const float* b1   = (const float*)d_in[5];
    const float* W2   = (const float*)d_in[6];
    const float* at2s = (const float*)d_in[7];
    const float* at2d = (const float*)d_in[8];
    const float* b2   = (const float*)d_in[9];
    float* out = (float*)d_out;

    int E = in_sizes[1] / 2;

    static float *p_h1 = nullptr, *p_as1, *p_ad1, *p_out1, *p_h2, *p_as2, *p_ad2, *p_out2;
    static int *p_cnt, *p_rowptr, *p_cursor, *p_col;
    if (!p_h1) {
        cudaGetSymbolAddress((void**)&p_h1, g_h1);
        cudaGetSymbolAddress((void**)&p_as1, g_as1);
        cudaGetSymbolAddress((void**)&p_ad1, g_ad1);
        cudaGetSymbolAddress((void**)&p_out1, g_out1);
        cudaGetSymbolAddress((void**)&p_h2, g_h2);
        cudaGetSymbolAddress((void**)&p_as2, g_as2);
        cudaGetSymbolAddress((void**)&p_ad2, g_ad2);
        cudaGetSymbolAddress((void**)&p_out2, g_out2);
        cudaGetSymbolAddress((void**)&p_cnt, g_cnt);
        cudaGetSymbolAddress((void**)&p_rowptr, g_rowptr);
        cudaGetSymbolAddress((void**)&p_cursor, g_cursor);
        cudaGetSymbolAddress((void**)&p_col, g_col);
    }

    const int TB = 256;
    auto blocks = [](int n, int tb) { return (n + tb - 1) / tb; };

    // ---- CSR build ----
    fill_int<<<blocks(NN, TB), TB>>>(p_cnt, 1, NN);
    count_dst<<<blocks(E, TB), TB>>>(ei, p_cnt, E);
    scan_rowptr<<<1, 1024>>>(p_cnt, p_rowptr, p_cursor);
    scatter_edges<<<blocks(E + NN, TB), TB>>>(ei, p_cursor, p_col, E);

    // ---- layer 1 ----
    {
        dim3 grid((HC1 + GBN - 1) / GBN, (NN + GBM - 1) / GBM);
        gemm_nt<<<grid, 256>>>(x, W1, p_h1, NN, HC1, NF);
    }
    att_kernel<H1><<<blocks(NN * H1, TB), TB>>>(p_h1, at1s, at1d, p_as1, p_ad1);
    gat_aggregate_l1<<<blocks(NN * 32, TB), TB>>>(p_rowptr, p_col, p_as1, p_ad1, p_h1, b1, p_out1);

    // ---- layer 2 ----
    {
        dim3 grid((C2 + GBN - 1) / GBN, (NN + GBM - 1) / GBM);
        gemm_nt<<<grid, 256>>>(p_out1, W2, p_h2, NN, C2, HC1);
    }
    att_kernel<1><<<blocks(NN, TB), TB>>>(p_h2, at2s, at2d, p_as2, p_ad2);
    gat_aggregate_l2<<<blocks(NN * 32, TB), TB>>>(p_rowptr, p_col, p_as2, p_ad2, p_h2, p_out2);

    // ---- log_softmax ----
    final_lsm<<<blocks(NN, TB), TB>>>(p_out2, b2, out, NN);
}

// round 6
// speedup vs baseline: 1.2200x; 1.0536x over previous
#include <cuda_runtime.h>
#include <math.h>

// ---------------- problem constants ----------------
#define NN   50000
#define NE   1600000
#define EPAD (NE + NN)
#define NF   512
#define H1   8
#define C1   16
#define HC1  128
#define C2   16

// ---------------- scratch (device globals) ----------------
__device__ float g_h1[NN * HC1];
__device__ float g_as1[NN * H1];
__device__ float g_ad1[NN * H1];
__device__ float g_out1[NN * HC1];
__device__ float g_h2[NN * C2];
__device__ float g_as2[NN];
__device__ float g_ad2[NN];
__device__ float g_out2[NN * C2];
__device__ int   g_cnt[NN];
__device__ int   g_rowptr[NN + 1];
__device__ int   g_cursor[NN];
__device__ int   g_col[EPAD];

// ================= CSR build =================
__global__ void fill_int(int* p, int v, int n) {
    int i = blockIdx.x * blockDim.x + threadIdx.x;
    if (i < n) p[i] = v;
}

__global__ void count_dst(const int* __restrict__ ei, int* __restrict__ cnt, int E) {
    int e = blockIdx.x * blockDim.x + threadIdx.x;
    if (e < E) atomicAdd(&cnt[ei[E + e]], 1);
}

// single-block exclusive scan over NN counts -> rowptr[NN+1] and cursor[NN]
__global__ void scan_rowptr(const int* __restrict__ cnt, int* __restrict__ rowptr,
                            int* __restrict__ cursor) {
    __shared__ int ssum[1024];
    const int T = 1024;
    const int PER = (NN + T - 1) / T;
    int tid = threadIdx.x;
    int start = tid * PER;
    int local = 0;
    for (int i = 0; i < PER; i++) {
        int idx = start + i;
        if (idx < NN) local += cnt[idx];
    }
    ssum[tid] = local;
    __syncthreads();
    for (int off = 1; off < T; off <<= 1) {
        int v = (tid >= off) ? ssum[tid - off] : 0;
        __syncthreads();
        ssum[tid] += v;
        __syncthreads();
    }
    int run = (tid == 0) ? 0 : ssum[tid - 1];
    for (int i = 0; i < PER; i++) {
        int idx = start + i;
        if (idx < NN) { rowptr[idx] = run; cursor[idx] = run; run += cnt[idx]; }
    }
    if (tid == T - 1) rowptr[NN] = ssum[T - 1];
}

__global__ void scatter_edges(const int* __restrict__ ei, int* __restrict__ cursor,
                              int* __restrict__ col, int E) {
    int i = blockIdx.x * blockDim.x + threadIdx.x;
    int tot = E + NN;
    if (i >= tot) return;
    int s, d;
    if (i < E) { s = ei[i]; d = ei[E + i]; } else { s = d = i - E; }
    int pos = atomicAdd(&cursor[d], 1);
    col[pos] = s;
}

// ================= SGEMM (NT) with register prefetch =================
#define GBM 128
#define GBN 128
#define GBK 8

__global__ __launch_bounds__(256, 2)
void gemm_nt(const float* __restrict__ A, const float* __restrict__ B,
             float* __restrict__ C, int M, int Nn, int K) {
    __shared__ float As[GBK][GBM];
    __shared__ float Bs[GBK][GBN];
    int t = threadIdx.x;
    int tx = t & 15, ty = t >> 4;
    int m0 = blockIdx.y * GBM, n0 = blockIdx.x * GBN;
    int lrow = t >> 1;
    int lk = (t & 1) * 4;

    float acc[8][8];
    #pragma unroll
    for (int i = 0; i < 8; i++)
        #pragma unroll
        for (int j = 0; j < 8; j++) acc[i][j] = 0.f;

    int am = m0 + lrow;
    int bn = n0 + lrow;
    const float* Ap = (am < M) ? &A[(size_t)am * K + lk] : nullptr;
    const float* Bp = (bn < Nn) ? &B[(size_t)bn * K + lk] : nullptr;

    float4 av = Ap ? *reinterpret_cast<const float4*>(Ap) : make_float4(0,0,0,0);
    float4 bv = Bp ? *reinterpret_cast<const float4*>(Bp) : make_float4(0,0,0,0);

    for (int k0 = 0; k0 < K; k0 += GBK) {
        As[lk + 0][lrow] = av.x; As[lk + 1][lrow] = av.y;
        As[lk + 2][lrow] = av.z; As[lk + 3][lrow] = av.w;
        Bs[lk + 0][lrow] = bv.x; Bs[lk + 1][lrow] = bv.y;
        Bs[lk + 2][lrow] = bv.z; Bs[lk + 3][lrow] = bv.w;
        __syncthreads();
        // prefetch next tile
        if (k0 + GBK < K) {
            av = Ap ? *reinterpret_cast<const float4*>(Ap + k0 + GBK) : make_float4(0,0,0,0);
            bv = Bp ? *reinterpret_cast<const float4*>(Bp + k0 + GBK) : make_float4(0,0,0,0);
        }
        #pragma unroll
        for (int k = 0; k < GBK; k++) {
            float a[8], b[8];
            float4 a0 = *reinterpret_cast<const float4*>(&As[k][ty * 8]);
            float4 a1 = *reinterpret_cast<const float4*>(&As[k][ty * 8 + 4]);
            float4 b0 = *reinterpret_cast<const float4*>(&Bs[k][tx * 8]);
            float4 b1 = *reinterpret_cast<const float4*>(&Bs[k][tx * 8 + 4]);
            a[0]=a0.x;a[1]=a0.y;a[2]=a0.z;a[3]=a0.w;a[4]=a1.x;a[5]=a1.y;a[6]=a1.z;a[7]=a1.w;
            b[0]=b0.x;b[1]=b0.y;b[2]=b0.z;b[3]=b0.w;b[4]=b1.x;b[5]=b1.y;b[6]=b1.z;b[7]=b1.w;
            #pragma unroll
            for (int i = 0; i < 8; i++)
                #pragma unroll
                for (int j = 0; j < 8; j++) acc[i][j] += a[i] * b[j];
        }
        __syncthreads();
    }
    #pragma unroll
    for (int i = 0; i < 8; i++) {
        int m = m0 + ty * 8 + i;
        if (m >= M) continue;
        #pragma unroll
        for (int j = 0; j < 8; j++) {
            int n = n0 + tx * 8 + j;
            if (n < Nn) C[(size_t)m * Nn + n] = acc[i][j];
        }
    }
}

// ================= attention coefficients (C=16, float4) =================
template<int H>
__global__ void att_kernel(const float* __restrict__ h, const float* __restrict__ att_s,
                           const float* __restrict__ att_d, float* __restrict__ as_,
                           float* __restrict__ ad_) {
    int idx = blockIdx.x * blockDim.x + threadIdx.x;
    if (idx >= NN * H) return;
    int hh = idx & (H - 1);
    const float4* hp = reinterpret_cast<const float4*>(h) + (size_t)idx * 4;
    const float4* sp = reinterpret_cast<const float4*>(att_s) + hh * 4;
    const float4* dp = reinterpret_cast<const float4*>(att_d) + hh * 4;
    float s = 0.f, d = 0.f;
    #pragma unroll
    for (int q = 0; q < 4; q++) {
        float4 v = hp[q], a = sp[q], b = dp[q];
        s += v.x * a.x + v.y * a.y + v.z * a.z + v.w * a.w;
        d += v.x * b.x + v.y * b.y + v.z * b.z + v.w * b.w;
    }
    as_[idx] = s;
    ad_[idx] = d;
}

// ================= layer-1 fused aggregate: one warp per dst, all 8 heads =================
__global__ __launch_bounds__(256)
void gat_aggregate_l1(const int* __restrict__ rowptr, const int* __restrict__ col,
                      const float* __restrict__ as_, const float* __restrict__ ad_,
                      const float* __restrict__ hfeat, const float* __restrict__ bias,
                      float* __restrict__ out) {
    int warp = (blockIdx.x * blockDim.x + threadIdx.x) >> 5;
    int lane = threadIdx.x & 31;
    if (warp >= NN) return;
    int dst = warp;
    int beg = rowptr[dst], end = rowptr[dst + 1];

    // per-dst attention offsets (uniform across warp)
    const float4* ad4 = reinterpret_cast<const float4*>(ad_) + (size_t)dst * 2;
    float4 adl = ad4[0], adh = ad4[1];
    float ad[8] = {adl.x, adl.y, adl.z, adl.w, adh.x, adh.y, adh.z, adh.w};

    const float4* as4 = reinterpret_cast<const float4*>(as_);

    // ---- sweep 1: online softmax (m, s) for all 8 heads ----
    float m[8], s[8];
    #pragma unroll
    for (int h = 0; h < 8; h++) { m[h] = -INFINITY; s[h] = 0.f; }

    for (int i = beg + lane; i < end; i += 32) {
        int src = col[i];
        float4 a0 = as4[(size_t)src * 2];
        float4 a1 = as4[(size_t)src * 2 + 1];
        float av[8] = {a0.x, a0.y, a0.z, a0.w, a1.x, a1.y, a1.z, a1.w};
        #pragma unroll
        for (int h = 0; h < 8; h++) {
            float v = av[h] + ad[h];
            v = v > 0.f ? v : 0.2f * v;
            float nm = fmaxf(m[h], v);
            s[h] = s[h] * __expf(m[h] - nm) + __expf(v - nm);  // m=-inf -> exp(-inf)=0, safe
            m[h] = nm;
        }
    }
    // warp butterfly combine (nan-safe for empty lanes)
    #pragma unroll
    for (int o = 16; o > 0; o >>= 1) {
        #pragma unroll
        for (int h = 0; h < 8; h++) {
            float om = __shfl_xor_sync(0xffffffffu, m[h], o);
            float os = __shfl_xor_sync(0xffffffffu, s[h], o);
            float nm = fmaxf(m[h], om);
            float e1 = (m[h] == nm) ? 1.f : __expf(m[h] - nm);
            float e2 = (om == nm)   ? 1.f : __expf(om - nm);
            s[h] = s[h] * e1 + os * e2;
            m[h] = nm;
        }
    }

    // lane-specific head selection (unrolled predicated, avoids spill)
    int myh = lane >> 2;
    float mh = m[0], sh = s[0], adhd = ad[0];
    #pragma unroll
    for (int h = 1; h < 8; h++)
        if (myh == h) { mh = m[h]; sh = s[h]; adhd = ad[h]; }
    float inv = 1.f / (sh + 1e-16f);

    // ---- sweep 2: weighted aggregate, lane owns channels [lane*4, lane*4+4) ----
    const float4* h4 = reinterpret_cast<const float4*>(hfeat);
    float4 acc = make_float4(0.f, 0.f, 0.f, 0.f);
    for (int i = beg; i < end; i++) {
        int src = col[i];
        float v = as_[src * 8 + myh] + adhd;
        v = v > 0.f ? v : 0.2f * v;
        float w = __expf(v - mh);
        float4 hv = h4[(size_t)src * 32 + lane];
        acc.x += w * hv.x; acc.y += w * hv.y; acc.z += w * hv.z; acc.w += w * hv.w;
    }
    const float4* b4 = reinterpret_cast<const float4*>(bias);
    float4 bb = b4[lane];
    float4 r;
    r.x = acc.x * inv + bb.x; r.y = acc.y * inv + bb.y;
    r.z = acc.z * inv + bb.z; r.w = acc.w * inv + bb.w;
    r.x = r.x > 0.f ? r.x : expm1f(r.x);
    r.y = r.y > 0.f ? r.y : expm1f(r.y);
    r.z = r.z > 0.f ? r.z : expm1f(r.z);
    r.w = r.w > 0.f ? r.w : expm1f(r.w);
    reinterpret_cast<float4*>(out)[(size_t)dst * 32 + lane] = r;
}

// ================= layer-2 aggregate: one warp per dst, H=1, C=16 =================
__global__ __launch_bounds__(256)
void gat_aggregate_l2(const int* __restrict__ rowptr, const int* __restrict__ col,
                      const float* __restrict__ as_, const float* __restrict__ ad_,
                      const float* __restrict__ hfeat, float* __restrict__ out) {
    int warp = (blockIdx.x * blockDim.x + threadIdx.x) >> 5;
    int lane = threadIdx.x & 31;
    if (warp >= NN) return;
    int dst = warp;
    int beg = rowptr[dst], end = rowptr[dst + 1];
    float adv = ad_[dst];

    // online softmax
    float m = -INFINITY, s = 0.f;
    for (int i = beg + lane; i < end; i += 32) {
        float v = as_[col[i]] + adv;
        v = v > 0.f ? v : 0.2f * v;
        float nm = fmaxf(m, v);
        s = s * __expf(m - nm) + __expf(v - nm);
        m = nm;
    }
    #pragma unroll
    for (int o = 16; o > 0; o >>= 1) {
        float om = __shfl_xor_sync(0xffffffffu, m, o);
        float os = __shfl_xor_sync(0xffffffffu, s, o);
        float nm = fmaxf(m, om);
        float e1 = (m == nm) ? 1.f : __expf(m - nm);
        float e2 = (om == nm) ? 1.f : __expf(om - nm);
        s = s * e1 + os * e2;
        m = nm;
    }
    float inv = 1.f / (s + 1e-16f);

    // aggregate: 2 edges/iter, 16 channels
    int c = lane & 15;
    int sub = lane >> 4;
    float acc = 0.f;
    for (int i = beg + sub; i < end; i += 2) {
        int src = col[i];
        float v = as_[src] + adv;
        v = v > 0.f ? v : 0.2f * v;
        float w = __expf(v - m);
        acc += w * hfeat[(size_t)src * 16 + c];
    }
    acc += __shfl_down_sync(0xffffffffu, acc, 16);
    if (lane < 16) out[(size_t)dst * 16 + c] = acc * inv;
}

// ================= final bias + log_softmax =================
__global__ void final_lsm(const float* __restrict__ in, const float* __restrict__ b,
                          float* __restrict__ out, int N) {
    int n = blockIdx.x * blockDim.x + threadIdx.x;
    if (n >= N) return;
    float v[C2];
    float m = -INFINITY;
    #pragma unroll
    for (int c = 0; c < C2; c++) {
        v[c] = in[(size_t)n * C2 + c] + b[c];
        m = fmaxf(m, v[c]);
    }
    float s = 0.f;
    #pragma unroll
    for (int c = 0; c < C2; c++) s += __expf(v[c] - m);
    float l = __logf(s);
    #pragma unroll
    for (int c = 0; c < C2; c++) out[(size_t)n * C2 + c] = v[c] - m - l;
}

// ================= launch =================
extern "C" void kernel_launch(void* const* d_in, const int* in_sizes, int n_in,
                              void* d_out, int out_size) {
    const float* x    = (const float*)d_in[0];
    const int*   ei   = (const int*)d_in[1];
    const float* W1   = (const float*)d_in[2];
    const float* at1s = (const float*)d_in[3];
    const float* at1d = (const float*)d_in[4];
    const float* b1   = (const float*)d_in[5];
    const float* W2   = (const float*)d_in[6];
    const float* at2s = (const float*)d_in[7];
    const float* at2d = (const float*)d_in[8];
    const float* b2   = (const float*)d_in[9];
    float* out = (float*)d_out;

    int E = in_sizes[1] / 2;

    static float *p_h1 = nullptr, *p_as1, *p_ad1, *p_out1, *p_h2, *p_as2, *p_ad2, *p_out2;
    static int *p_cnt, *p_rowptr, *p_cursor, *p_col;
    if (!p_h1) {
        cudaGetSymbolAddress((void**)&p_h1, g_h1);
        cudaGetSymbolAddress((void**)&p_as1, g_as1);
        cudaGetSymbolAddress((void**)&p_ad1, g_ad1);
        cudaGetSymbolAddress((void**)&p_out1, g_out1);
        cudaGetSymbolAddress((void**)&p_h2, g_h2);
        cudaGetSymbolAddress((void**)&p_as2, g_as2);
        cudaGetSymbolAddress((void**)&p_ad2, g_ad2);
        cudaGetSymbolAddress((void**)&p_out2, g_out2);
        cudaGetSymbolAddress((void**)&p_cnt, g_cnt);
        cudaGetSymbolAddress((void**)&p_rowptr, g_rowptr);
        cudaGetSymbolAddress((void**)&p_cursor, g_cursor);
        cudaGetSymbolAddress((void**)&p_col, g_col);
    }

    const int TB = 256;
    auto blocks = [](int n, int tb) { return (n + tb - 1) / tb; };

    // ---- CSR build ----
    fill_int<<<blocks(NN, TB), TB>>>(p_cnt, 1, NN);
    count_dst<<<blocks(E, TB), TB>>>(ei, p_cnt, E);
    scan_rowptr<<<1, 1024>>>(p_cnt, p_rowptr, p_cursor);
    scatter_edges<<<blocks(E + NN, TB), TB>>>(ei, p_cursor, p_col, E);

    // ---- layer 1 ----
    {
        dim3 grid((HC1 + GBN - 1) / GBN, (NN + GBM - 1) / GBM);
        gemm_nt<<<grid, 256>>>(x, W1, p_h1, NN, HC1, NF);
    }
    att_kernel<H1><<<blocks(NN * H1, TB), TB>>>(p_h1, at1s, at1d, p_as1, p_ad1);
    gat_aggregate_l1<<<blocks(NN * 32, TB), TB>>>(p_rowptr, p_col, p_as1, p_ad1, p_h1, b1, p_out1);

    // ---- layer 2 ----
    {
        dim3 grid((C2 + GBN - 1) / GBN, (NN + GBM - 1) / GBM);
        gemm_nt<<<grid, 256>>>(p_out1, W2, p_h2, NN, C2, HC1);
    }
    att_kernel<1><<<blocks(NN, TB), TB>>>(p_h2, at2s, at2d, p_as2, p_ad2);
    gat_aggregate_l2<<<blocks(NN * 32, TB), TB>>>(p_rowptr, p_col, p_as2, p_ad2, p_h2, p_out2);

    // ---- log_softmax ----
    final_lsm<<<blocks(NN, TB), TB>>>(p_out2, b2, out, NN);
}